// round 2
// baseline (speedup 1.0000x reference)
#include <cuda_runtime.h>

#define NDIM 1000
#define PDIM 50000
#define ZDIM 10
#define LDIM 5

#define NSPLIT 4
#define NCHUNK (NDIM / NSPLIT)                        // 250
#define K1_THREADS 256
#define K1_PTILE (K1_THREADS * 4)                     // 1024
#define K1_PTILES ((PDIM + K1_PTILE - 1) / K1_PTILE)  // 49
#define K1_MAIN (K1_PTILES * NSPLIT)                  // 196

#define K2_BLOCKS 98
#define K2_THREADS 256
#define NSTEPS (ZDIM * LDIM)                          // 50

#define OUT_VW_OFF (LDIM * ZDIM * PDIM)               // 250000
#define OUT_AL_OFF (OUT_VW_OFF + LDIM * ZDIM)         // 250050

// Static device scratch (no runtime allocation allowed)
__device__ __align__(16) float g_ztrp[NSPLIT][ZDIM][PDIM];   // 8 MB partials
__device__ float g_mzz[ZDIM * ZDIM];
// Per-step, per-block publication slot, padded to 128B (own cache line):
// [0]=m, [1]=s, [2]=flag. Flags zeroed by k1 each launch.
__device__ __align__(128) float g_slot[NSTEPS][K2_BLOCKS][32];

// ---- fence-free release/acquire publication helpers ----
__device__ __forceinline__ void publish_slot(float* slot, float m, float s) {
    asm volatile("st.global.v2.f32 [%0], {%1, %2};" :: "l"(slot), "f"(m), "f"(s) : "memory");
    asm volatile("st.release.gpu.global.f32 [%0], %1;" :: "l"(slot + 2), "f"(1.0f) : "memory");
}
__device__ __forceinline__ float ld_acquire(const float* p) {
    float v;
    asm volatile("ld.acquire.gpu.global.f32 %0, [%1];" : "=f"(v) : "l"(p) : "memory");
    return v;
}

// ---------------------------------------------------------------------------
// Kernel 1: ZtR partials (ZtR[k,p] = sum_n mean_z[n,k]*data[n,p]) split over
// NSPLIT n-chunks, plus mean_zz, vw output, and slot-flag reset.
// ---------------------------------------------------------------------------
__global__ __launch_bounds__(K1_THREADS)
void k1_ztr(const float* __restrict__ data,
            const float* __restrict__ mean_z,
            const float* __restrict__ var_z,
            const float* __restrict__ tau_0,
            const float* __restrict__ tau_p,
            float* __restrict__ out_vw)
{
    const int b = blockIdx.x;
    const int tid = threadIdx.x;

    if (b == K1_MAIN) {
        // Aux block: reset slot flags, compute mean_zz = Z^T Z + N*var_z, write vw.
        for (int i = tid; i < NSTEPS * K2_BLOCKS; i += K1_THREADS)
            g_slot[i / K2_BLOCKS][i % K2_BLOCKS][2] = 0.f;
        __shared__ float s_mzz[ZDIM * ZDIM];
        if (tid < ZDIM * ZDIM) {
            int i = tid / ZDIM, j = tid % ZDIM;
            float s = 0.f;
            for (int n = 0; n < NDIM; n++)
                s += mean_z[n * ZDIM + i] * mean_z[n * ZDIM + j];
            s += (float)NDIM * var_z[i * ZDIM + j];
            s_mzz[tid] = s;
            g_mzz[tid] = s;
        }
        __syncthreads();
        if (tid < LDIM * ZDIM) {
            int l = tid / ZDIM, k = tid % ZDIM;
            float tau = tau_p[0];
            out_vw[tid] = 1.0f / (tau * s_mzz[k * ZDIM + k] + tau_0[l * ZDIM + k]);
        }
        return;
    }

    const int pt = b % K1_PTILES;
    const int c  = b / K1_PTILES;

    // mean_z chunk in shared, rows padded to 12 floats for float4 reads.
    __shared__ __align__(16) float s_z[NCHUNK][12];
    for (int i = tid; i < NCHUNK * ZDIM; i += K1_THREADS) {
        int n = i / ZDIM, kk = i % ZDIM;
        s_z[n][kk] = mean_z[(c * NCHUNK + n) * ZDIM + kk];
    }
    __syncthreads();

    const int p0 = pt * K1_PTILE + tid * 4;
    if (p0 >= PDIM) return;   // P % 4 == 0 -> p0..p0+3 all valid when p0 < P

    float4 acc[ZDIM];
#pragma unroll
    for (int k = 0; k < ZDIM; k++) acc[k] = make_float4(0.f, 0.f, 0.f, 0.f);

    const float* dptr = data + (size_t)c * NCHUNK * PDIM + p0;
#pragma unroll 4
    for (int n = 0; n < NCHUNK; n++) {
        float4 d = __ldcs(reinterpret_cast<const float4*>(dptr + (size_t)n * PDIM));
        const float4* zr = reinterpret_cast<const float4*>(s_z[n]);
        float4 z0 = zr[0], z1 = zr[1], z2 = zr[2];
        float zk[ZDIM] = {z0.x, z0.y, z0.z, z0.w, z1.x, z1.y, z1.z, z1.w, z2.x, z2.y};
#pragma unroll
        for (int k = 0; k < ZDIM; k++) {
            acc[k].x = fmaf(zk[k], d.x, acc[k].x);
            acc[k].y = fmaf(zk[k], d.y, acc[k].y);
            acc[k].z = fmaf(zk[k], d.z, acc[k].z);
            acc[k].w = fmaf(zk[k], d.w, acc[k].w);
        }
    }
#pragma unroll
    for (int k = 0; k < ZDIM; k++)
        *reinterpret_cast<float4*>(&g_ztrp[c][k][p0]) = acc[k];
}

// ---------------------------------------------------------------------------
// Kernel 2: persistent serial coordinate-descent sweep. 98 co-resident CTAs,
// each thread owns 2 p-columns. Fence-free per-step rendezvous.
// ---------------------------------------------------------------------------
__global__ __launch_bounds__(K2_THREADS)
void k2_loop(const float* __restrict__ mw_in,
             const float* __restrict__ al_in,
             const float* __restrict__ pi,
             const float* __restrict__ tau_0,
             const float* __restrict__ tau_p,
             float* __restrict__ out)
{
    const int tid  = threadIdx.x;
    const int b    = blockIdx.x;
    const int wid  = tid >> 5;
    const int lane = tid & 31;

    float* out_mw = out;
    float* out_al = out + OUT_AL_OFF;

    __shared__ float s_mzz[ZDIM * ZDIM];
    __shared__ float s_t0[LDIM * ZDIM];
    __shared__ float s_red[8][2];
    __shared__ float s_ms[2];

    if (tid < ZDIM * ZDIM) s_mzz[tid] = g_mzz[tid];
    if (tid < LDIM * ZDIM) s_t0[tid] = tau_0[tid];
    const float tau = tau_p[0];

    const int p0 = b * (K2_THREADS * 2) + tid;     // always < PDIM (max 49919)
    const int p1 = p0 + K2_THREADS;
    const bool v1 = (p1 < PDIM);

    // Per-thread register state: W columns, ZtR columns, raw pi for its two p's.
    float W[ZDIM][2], Zt[ZDIM][2], pir[ZDIM][2];
#pragma unroll
    for (int k = 0; k < ZDIM; k++) {
        {
            float zt = 0.f;
#pragma unroll
            for (int c = 0; c < NSPLIT; c++) zt += g_ztrp[c][k][p0];
            float w = 0.f;
#pragma unroll
            for (int l = 0; l < LDIM; l++) {
                size_t idx = (size_t)(l * ZDIM + k) * PDIM + p0;
                w = fmaf(mw_in[idx], al_in[idx], w);
            }
            Zt[k][0] = zt; W[k][0] = w;
            pir[k][0] = pi[(size_t)k * PDIM + p0];
        }
        if (v1) {
            float zt = 0.f;
#pragma unroll
            for (int c = 0; c < NSPLIT; c++) zt += g_ztrp[c][k][p1];
            float w = 0.f;
#pragma unroll
            for (int l = 0; l < LDIM; l++) {
                size_t idx = (size_t)(l * ZDIM + k) * PDIM + p1;
                w = fmaf(mw_in[idx], al_in[idx], w);
            }
            Zt[k][1] = zt; W[k][1] = w;
            pir[k][1] = pi[(size_t)k * PDIM + p1];
        } else { Zt[k][1] = 0.f; W[k][1] = 0.f; pir[k][1] = 1.f; }
    }
    __syncthreads();

#pragma unroll
    for (int k = 0; k < ZDIM; k++) {
        const float Ezz = s_mzz[k * ZDIM + k];
        float Rt[2], Wk[2];
#pragma unroll
        for (int e = 0; e < 2; e++) {
            float s = Zt[k][e];
#pragma unroll
            for (int j = 0; j < ZDIM; j++)
                s -= s_mzz[k * ZDIM + j] * W[j][e];
            Rt[e] = s + Ezz * W[k][e];            // = ZtR[k] - sum_{j!=k} mzz[k,j]*W[j]
            Wk[e] = W[k][e];
        }
        const float lpi0 = __logf(pir[k][0]);
        const float lpi1 = __logf(pir[k][1]);

        // preload mw*al products for l=0 of this k
        float pw0, pw1;
        {
            size_t idx = (size_t)k * PDIM + p0;
            pw0 = mw_in[idx] * al_in[idx];
            pw1 = v1 ? mw_in[idx + K2_THREADS] * al_in[idx + K2_THREADS] : 0.f;
        }

        for (int l = 0; l < LDIM; l++) {
            const int step = k * LDIM + l;

            // issue raw loads for next l early (consumed after the rendezvous)
            const int ln = (l + 1 < LDIM) ? l + 1 : l;
            const size_t nidx = (size_t)(ln * ZDIM + k) * PDIM + p0;
            float nm0 = mw_in[nidx], na0 = al_in[nidx];
            float nm1 = 0.f, na1 = 0.f;
            if (v1) { nm1 = mw_in[nidx + K2_THREADS]; na1 = al_in[nidx + K2_THREADS]; }

            const float t0    = s_t0[l * ZDIM + k];
            const float u_var = 1.f / (tau * Ezz + t0);
            const float s2    = 1.f / (Ezz * tau);
            const float s0inv = 1.f / t0;
            // logit = log(pi) + C2*r^2  (constant part of log_bf cancels in softmax)
            const float C2 = 0.5f * (tau / Ezz) * (s0inv / (s2 + s0inv));

            float Wkl0 = Wk[0] - pw0;
            float r0   = Rt[0] - Ezz * Wkl0;
            float lg0  = fmaf(C2 * r0, r0, lpi0);
            float Wkl1, r1, lg1;
            if (v1) {
                Wkl1 = Wk[1] - pw1;
                r1   = Rt[1] - Ezz * Wkl1;
                lg1  = fmaf(C2 * r1, r1, lpi1);
            } else { Wkl1 = 0.f; r1 = 0.f; lg1 = -1e30f; }

            // ---- warp-level online softmax reduce (m, s) ----
            float m = fmaxf(lg0, lg1);
            float s = __expf(lg0 - m) + __expf(lg1 - m);
#pragma unroll
            for (int o = 16; o > 0; o >>= 1) {
                float mo = __shfl_xor_sync(0xffffffffu, m, o);
                float so = __shfl_xor_sync(0xffffffffu, s, o);
                float nm = fmaxf(m, mo);
                s = s * __expf(m - nm) + so * __expf(mo - nm);
                m = nm;
            }
            if (lane == 0) { s_red[wid][0] = m; s_red[wid][1] = s; }
            __syncthreads();

            if (wid == 0) {
                // block-level reduce over 8 warp results
                float mb = (lane < 8) ? s_red[lane][0] : -1e30f;
                float sb = (lane < 8) ? s_red[lane][1] : 0.f;
#pragma unroll
                for (int o = 4; o > 0; o >>= 1) {
                    float mo = __shfl_xor_sync(0xffffffffu, mb, o);
                    float so = __shfl_xor_sync(0xffffffffu, sb, o);
                    float nm = fmaxf(mb, mo);
                    sb = sb * __expf(mb - nm) + so * __expf(mo - nm);
                    mb = nm;
                }
                if (lane == 0)
                    publish_slot(&g_slot[step][b][0], mb, sb);

                // ---- grid-level combine: poll flags, combine partials ----
                float gm = -1e30f, gs = 0.f;
                for (int si = lane; si < K2_BLOCKS; si += 32) {
                    float* slot = &g_slot[step][si][0];
                    while (ld_acquire(slot + 2) == 0.f) { }
                    float mp = __ldcg(slot);
                    float sp = __ldcg(slot + 1);
                    float nm = fmaxf(gm, mp);
                    gs = gs * __expf(gm - nm) + sp * __expf(mp - nm);
                    gm = nm;
                }
#pragma unroll
                for (int o = 16; o > 0; o >>= 1) {
                    float mo = __shfl_xor_sync(0xffffffffu, gm, o);
                    float so = __shfl_xor_sync(0xffffffffu, gs, o);
                    float nm = fmaxf(gm, mo);
                    gs = gs * __expf(gm - nm) + so * __expf(mo - nm);
                    gm = nm;
                }
                if (lane == 0) { s_ms[0] = gm; s_ms[1] = gs; }
            }
            __syncthreads();
            const float gm = s_ms[0];
            const float gs = s_ms[1];

            // ---- normalize, update Wk, store outputs ----
            {
                float a  = __expf(lg0 - gm) / gs;
                float um = tau * u_var * r0;
                Wk[0] = Wkl0 + um * a;
                size_t idx = (size_t)(l * ZDIM + k) * PDIM + p0;
                out_mw[idx] = um;
                out_al[idx] = a;
            }
            if (v1) {
                float a  = __expf(lg1 - gm) / gs;
                float um = tau * u_var * r1;
                Wk[1] = Wkl1 + um * a;
                size_t idx = (size_t)(l * ZDIM + k) * PDIM + p1;
                out_mw[idx] = um;
                out_al[idx] = a;
            }

            // rotate prefetched products into place for next l
            pw0 = nm0 * na0;
            pw1 = nm1 * na1;
        }
        W[k][0] = Wk[0];
        W[k][1] = Wk[1];
    }
}

// ---------------------------------------------------------------------------
extern "C" void kernel_launch(void* const* d_in, const int* in_sizes, int n_in,
                              void* d_out, int out_size)
{
    (void)in_sizes; (void)n_in; (void)out_size;
    const float* data   = (const float*)d_in[0];
    const float* mean_z = (const float*)d_in[1];
    const float* var_z  = (const float*)d_in[2];
    const float* mean_w = (const float*)d_in[3];
    // d_in[4] = var_w (unused: vw output fully overwritten)
    const float* alpha  = (const float*)d_in[5];
    const float* tau_0  = (const float*)d_in[6];
    const float* pi     = (const float*)d_in[7];
    const float* tau    = (const float*)d_in[8];
    float* out = (float*)d_out;

    k1_ztr<<<K1_MAIN + 1, K1_THREADS>>>(data, mean_z, var_z, tau_0, tau,
                                        out + OUT_VW_OFF);
    k2_loop<<<K2_BLOCKS, K2_THREADS>>>(mean_w, alpha, pi, tau_0, tau, out);
}

// round 3
// speedup vs baseline: 1.8497x; 1.8497x over previous
#include <cuda_runtime.h>

#define NDIM 1000
#define PDIM 50000
#define ZDIM 10
#define LDIM 5

#define NSPLIT 8
#define NCHUNK (NDIM / NSPLIT)                        // 125
#define K1_THREADS 256
#define K1_PTILE (K1_THREADS * 4)                     // 1024
#define K1_PTILES ((PDIM + K1_PTILE - 1) / K1_PTILE)  // 49
#define K1_MAIN (K1_PTILES * NSPLIT)                  // 392

#define K2_BLOCKS 98
#define K2_THREADS 256
#define NSTEPS (ZDIM * LDIM)                          // 50

#define OUT_VW_OFF (LDIM * ZDIM * PDIM)               // 250000
#define OUT_AL_OFF (OUT_VW_OFF + LDIM * ZDIM)         // 250050

// Static device scratch (no runtime allocation allowed)
__device__ __align__(16) float g_ztrp[NSPLIT][ZDIM][PDIM];   // 16 MB partials
__device__ float g_mzz[ZDIM * ZDIM];
__device__ __align__(128) float2 g_part[NSTEPS][128];        // per-step (m, s) per block
__device__ int g_cnt[NSTEPS];                                // per-step arrival counters

// ---- release/acquire rendezvous helpers (no MEMBAR) ----
__device__ __forceinline__ void publish(float2* slot, int* cnt, float m, float s) {
    asm volatile("st.global.v2.f32 [%0], {%1, %2};" :: "l"(slot), "f"(m), "f"(s) : "memory");
    // release-ordering: the v2 store is visible at gpu scope before the increment
    asm volatile("red.release.gpu.global.add.u32 [%0], 1;" :: "l"(cnt) : "memory");
}
__device__ __forceinline__ unsigned ld_acquire_u32(const int* p) {
    unsigned v;
    asm volatile("ld.acquire.gpu.global.u32 %0, [%1];" : "=r"(v) : "l"(p) : "memory");
    return v;
}

// online-softmax pair combine: (m,s) <- comb((m,s),(mo,so))
__device__ __forceinline__ void comb(float& m, float& s, float mo, float so) {
    float nm = fmaxf(m, mo);
    s = s * __expf(m - nm) + so * __expf(mo - nm);
    m = nm;
}

// ---------------------------------------------------------------------------
// Kernel 1: ZtR partials (ZtR[k,p] = sum_n mean_z[n,k]*data[n,p]) split over
// NSPLIT n-chunks, plus mean_zz, vw output, and counter reset.
// ---------------------------------------------------------------------------
__global__ __launch_bounds__(K1_THREADS)
void k1_ztr(const float* __restrict__ data,
            const float* __restrict__ mean_z,
            const float* __restrict__ var_z,
            const float* __restrict__ tau_0,
            const float* __restrict__ tau_p,
            float* __restrict__ out_vw)
{
    const int b = blockIdx.x;
    const int tid = threadIdx.x;

    if (b == K1_MAIN) {
        // Aux block: reset counters, compute mean_zz = Z^T Z + N*var_z, write vw.
        if (tid < NSTEPS) g_cnt[tid] = 0;
        __shared__ float s_mzz[ZDIM * ZDIM];
        if (tid < ZDIM * ZDIM) {
            int i = tid / ZDIM, j = tid % ZDIM;
            float s = 0.f;
            for (int n = 0; n < NDIM; n++)
                s += mean_z[n * ZDIM + i] * mean_z[n * ZDIM + j];
            s += (float)NDIM * var_z[i * ZDIM + j];
            s_mzz[tid] = s;
            g_mzz[tid] = s;
        }
        __syncthreads();
        if (tid < LDIM * ZDIM) {
            int l = tid / ZDIM, k = tid % ZDIM;
            float tau = tau_p[0];
            out_vw[tid] = 1.0f / (tau * s_mzz[k * ZDIM + k] + tau_0[l * ZDIM + k]);
        }
        return;
    }

    const int pt = b % K1_PTILES;
    const int c  = b / K1_PTILES;

    // mean_z chunk in shared, rows padded to 12 floats for float4 reads.
    __shared__ __align__(16) float s_z[NCHUNK][12];
    for (int i = tid; i < NCHUNK * ZDIM; i += K1_THREADS) {
        int n = i / ZDIM, kk = i % ZDIM;
        s_z[n][kk] = mean_z[(c * NCHUNK + n) * ZDIM + kk];
    }
    __syncthreads();

    const int p0 = pt * K1_PTILE + tid * 4;
    if (p0 >= PDIM) return;   // P % 4 == 0 -> p0..p0+3 all valid when p0 < P

    float4 acc[ZDIM];
#pragma unroll
    for (int k = 0; k < ZDIM; k++) acc[k] = make_float4(0.f, 0.f, 0.f, 0.f);

    const float* dptr = data + (size_t)c * NCHUNK * PDIM + p0;
#pragma unroll 2
    for (int n = 0; n < NCHUNK; n++) {
        float4 d = *reinterpret_cast<const float4*>(dptr + (size_t)n * PDIM);
        const float4* zr = reinterpret_cast<const float4*>(s_z[n]);
        float4 z0 = zr[0], z1 = zr[1], z2 = zr[2];
        float zk[ZDIM] = {z0.x, z0.y, z0.z, z0.w, z1.x, z1.y, z1.z, z1.w, z2.x, z2.y};
#pragma unroll
        for (int k = 0; k < ZDIM; k++) {
            acc[k].x = fmaf(zk[k], d.x, acc[k].x);
            acc[k].y = fmaf(zk[k], d.y, acc[k].y);
            acc[k].z = fmaf(zk[k], d.z, acc[k].z);
            acc[k].w = fmaf(zk[k], d.w, acc[k].w);
        }
    }
#pragma unroll
    for (int k = 0; k < ZDIM; k++)
        *reinterpret_cast<float4*>(&g_ztrp[c][k][p0]) = acc[k];
}

// ---------------------------------------------------------------------------
// Kernel 2: persistent serial coordinate-descent sweep. 98 co-resident CTAs,
// each thread owns 2 p-columns. Release/acquire counter rendezvous per step.
// ---------------------------------------------------------------------------
__global__ __launch_bounds__(K2_THREADS)
void k2_loop(const float* __restrict__ mw_in,
             const float* __restrict__ al_in,
             const float* __restrict__ pi,
             const float* __restrict__ tau_0,
             const float* __restrict__ tau_p,
             float* __restrict__ out)
{
    const int tid  = threadIdx.x;
    const int b    = blockIdx.x;
    const int wid  = tid >> 5;
    const int lane = tid & 31;

    float* out_mw = out;
    float* out_al = out + OUT_AL_OFF;

    __shared__ float s_mzz[ZDIM * ZDIM];
    __shared__ float s_t0[LDIM * ZDIM];
    __shared__ float s_red[8][2];
    __shared__ float s_ms[2];

    if (tid < ZDIM * ZDIM) s_mzz[tid] = g_mzz[tid];
    if (tid < LDIM * ZDIM) s_t0[tid] = tau_0[tid];
    const float tau = tau_p[0];

    const int p0 = b * (K2_THREADS * 2) + tid;     // always < PDIM (max 49919)
    const int p1 = p0 + K2_THREADS;
    const bool v1 = (p1 < PDIM);

    // Per-thread register state: W columns, ZtR columns, log(pi) for its two p's.
    float W[ZDIM][2], Zt[ZDIM][2], lpi[ZDIM][2];
#pragma unroll
    for (int k = 0; k < ZDIM; k++) {
        {
            float zt = 0.f;
#pragma unroll
            for (int c = 0; c < NSPLIT; c++) zt += g_ztrp[c][k][p0];
            float w = 0.f;
#pragma unroll
            for (int l = 0; l < LDIM; l++) {
                size_t idx = (size_t)(l * ZDIM + k) * PDIM + p0;
                w = fmaf(mw_in[idx], al_in[idx], w);
            }
            Zt[k][0] = zt; W[k][0] = w;
            lpi[k][0] = __logf(pi[(size_t)k * PDIM + p0]);
        }
        if (v1) {
            float zt = 0.f;
#pragma unroll
            for (int c = 0; c < NSPLIT; c++) zt += g_ztrp[c][k][p1];
            float w = 0.f;
#pragma unroll
            for (int l = 0; l < LDIM; l++) {
                size_t idx = (size_t)(l * ZDIM + k) * PDIM + p1;
                w = fmaf(mw_in[idx], al_in[idx], w);
            }
            Zt[k][1] = zt; W[k][1] = w;
            lpi[k][1] = __logf(pi[(size_t)k * PDIM + p1]);
        } else { Zt[k][1] = 0.f; W[k][1] = 0.f; lpi[k][1] = 0.f; }
    }
    __syncthreads();

#pragma unroll
    for (int k = 0; k < ZDIM; k++) {
        const float Ezz = s_mzz[k * ZDIM + k];
        float Rt[2], Wk[2];
#pragma unroll
        for (int e = 0; e < 2; e++) {
            float s = Zt[k][e];
#pragma unroll
            for (int j = 0; j < ZDIM; j++)
                s -= s_mzz[k * ZDIM + j] * W[j][e];
            Rt[e] = s + Ezz * W[k][e];            // = ZtR[k] - sum_{j!=k} mzz[k,j]*W[j]
            Wk[e] = W[k][e];
        }

        // preload mw*al products for l=0 of this k
        float pw0, pw1;
        {
            size_t idx = (size_t)k * PDIM + p0;
            pw0 = mw_in[idx] * al_in[idx];
            pw1 = v1 ? mw_in[idx + K2_THREADS] * al_in[idx + K2_THREADS] : 0.f;
        }

        for (int l = 0; l < LDIM; l++) {
            const int step = k * LDIM + l;

            // issue raw loads for next l early (consumed at loop end)
            const int ln = (l + 1 < LDIM) ? l + 1 : l;
            const size_t nidx = (size_t)(ln * ZDIM + k) * PDIM + p0;
            float nm0 = mw_in[nidx], na0 = al_in[nidx];
            float nm1 = 0.f, na1 = 0.f;
            if (v1) { nm1 = mw_in[nidx + K2_THREADS]; na1 = al_in[nidx + K2_THREADS]; }

            const float t0    = s_t0[l * ZDIM + k];
            const float u_var = 1.f / (tau * Ezz + t0);
            const float s2    = 1.f / (Ezz * tau);
            const float s0inv = 1.f / t0;
            // logit = log(pi) + C2*r^2  (constant part of log_bf cancels in softmax)
            const float C2 = 0.5f * (tau / Ezz) * (s0inv / (s2 + s0inv));

            float Wkl0 = Wk[0] - pw0;
            float r0   = Rt[0] - Ezz * Wkl0;
            float lg0  = fmaf(C2 * r0, r0, lpi[k][0]);
            float Wkl1, r1, lg1;
            if (v1) {
                Wkl1 = Wk[1] - pw1;
                r1   = Rt[1] - Ezz * Wkl1;
                lg1  = fmaf(C2 * r1, r1, lpi[k][1]);
            } else { Wkl1 = 0.f; r1 = 0.f; lg1 = -1e30f; }

            // ---- warp-level online softmax reduce (m, s) ----
            float m = fmaxf(lg0, lg1);
            float s = __expf(lg0 - m) + __expf(lg1 - m);
#pragma unroll
            for (int o = 16; o > 0; o >>= 1) {
                float mo = __shfl_xor_sync(0xffffffffu, m, o);
                float so = __shfl_xor_sync(0xffffffffu, s, o);
                comb(m, s, mo, so);
            }
            if (lane == 0) { s_red[wid][0] = m; s_red[wid][1] = s; }
            __syncthreads();

            if (wid == 0) {
                // block-level reduce over 8 warp results
                float mb = (lane < 8) ? s_red[lane][0] : -1e30f;
                float sb = (lane < 8) ? s_red[lane][1] : 0.f;
#pragma unroll
                for (int o = 4; o > 0; o >>= 1) {
                    float mo = __shfl_xor_sync(0xffffffffu, mb, o);
                    float so = __shfl_xor_sync(0xffffffffu, sb, o);
                    comb(mb, sb, mo, so);
                }
                if (lane == 0) {
                    publish(&g_part[step][b], &g_cnt[step], mb, sb);
                    // single poller: acquire-poll the per-step counter
                    while (ld_acquire_u32(&g_cnt[step]) < K2_BLOCKS) { }
                }
                __syncwarp();

                // ---- grid combine: 4 independent L2 reads/lane, tree + shuffles ----
                float2 v0 = __ldcg(&g_part[step][lane]);
                float2 v1g = __ldcg(&g_part[step][lane + 32]);
                float2 v2 = __ldcg(&g_part[step][lane + 64]);
                float2 v3 = (lane + 96 < K2_BLOCKS) ? __ldcg(&g_part[step][lane + 96])
                                                    : make_float2(-1e30f, 0.f);
                float ma = v0.x, sa = v0.y;
                comb(ma, sa, v1g.x, v1g.y);
                float mc = v2.x, sc = v2.y;
                comb(mc, sc, v3.x, v3.y);
                comb(ma, sa, mc, sc);
#pragma unroll
                for (int o = 16; o > 0; o >>= 1) {
                    float mo = __shfl_xor_sync(0xffffffffu, ma, o);
                    float so = __shfl_xor_sync(0xffffffffu, sa, o);
                    comb(ma, sa, mo, so);
                }
                if (lane == 0) { s_ms[0] = ma; s_ms[1] = sa; }
            }
            __syncthreads();
            const float gm = s_ms[0];
            const float gs = s_ms[1];

            // ---- normalize, update Wk, store outputs ----
            {
                float a  = __expf(lg0 - gm) / gs;
                float um = tau * u_var * r0;
                Wk[0] = Wkl0 + um * a;
                size_t idx = (size_t)(l * ZDIM + k) * PDIM + p0;
                out_mw[idx] = um;
                out_al[idx] = a;
            }
            if (v1) {
                float a  = __expf(lg1 - gm) / gs;
                float um = tau * u_var * r1;
                Wk[1] = Wkl1 + um * a;
                size_t idx = (size_t)(l * ZDIM + k) * PDIM + p1;
                out_mw[idx] = um;
                out_al[idx] = a;
            }

            // rotate prefetched products into place for next l
            pw0 = nm0 * na0;
            pw1 = nm1 * na1;
        }
        W[k][0] = Wk[0];
        W[k][1] = Wk[1];
    }
}

// ---------------------------------------------------------------------------
extern "C" void kernel_launch(void* const* d_in, const int* in_sizes, int n_in,
                              void* d_out, int out_size)
{
    (void)in_sizes; (void)n_in; (void)out_size;
    const float* data   = (const float*)d_in[0];
    const float* mean_z = (const float*)d_in[1];
    const float* var_z  = (const float*)d_in[2];
    const float* mean_w = (const float*)d_in[3];
    // d_in[4] = var_w (unused: vw output fully overwritten)
    const float* alpha  = (const float*)d_in[5];
    const float* tau_0  = (const float*)d_in[6];
    const float* pi     = (const float*)d_in[7];
    const float* tau    = (const float*)d_in[8];
    float* out = (float*)d_out;

    k1_ztr<<<K1_MAIN + 1, K1_THREADS>>>(data, mean_z, var_z, tau_0, tau,
                                        out + OUT_VW_OFF);
    k2_loop<<<K2_BLOCKS, K2_THREADS>>>(mean_w, alpha, pi, tau_0, tau, out);
}